// round 1
// baseline (speedup 1.0000x reference)
#include <cuda_runtime.h>
#include <cuda_bf16.h>
#include <cstdint>

#define BB 4
#define NN 16384
#define KK 16
#define CC 64
#define ROWS (BB * NN)        // 65536
#define GROUPS (ROWS / 4)     // 16384 groups of 4 rows
#define TOTAL ((size_t)ROWS * CC)

// ---------------- scratch (static device globals; no runtime allocation) ----
__device__ float g_ek[TOTAL];    // exp(-(features@kw+kb)/8)
__device__ float g_v [TOTAL];    // features@vw+vb
__device__ float g_ctx[TOTAL];   // attention context
__device__ float g_h [TOTAL];    // context@fw+fb (pre-BN)
__device__ float g_sum [CC];     // BN stats accumulators
__device__ float g_sum2[CC];

// ============================================================================
// Kernel 1: fused k/v projection.  k -> ek = exp(-k/8) stored directly.
// Layout: 256 threads, thread owns (kq = tid>>6, c = tid&63); holds 16 weights
// per matrix in registers; x is broadcast from smem (LDS.128, all lanes same
// address -> conflict-free broadcast). 4 rows per barrier round.
// Block 0 also zeroes the BN accumulators for this launch.
// ============================================================================
__global__ void __launch_bounds__(256) proj_kernel(
    const float* __restrict__ feat,
    const float* __restrict__ kw, const float* __restrict__ kb,
    const float* __restrict__ vw, const float* __restrict__ vb)
{
    __shared__ float xs[256];          // 4 rows x 64
    __shared__ float psK[16 * 64];     // partials: (row*4+kq, c)
    __shared__ float psV[16 * 64];

    const int tid = threadIdx.x;
    const int kq  = tid >> 6;   // 0..3 : which 16-slice of the K dim
    const int c   = tid & 63;   // output channel

    if (blockIdx.x == 0 && tid < CC) { g_sum[tid] = 0.f; g_sum2[tid] = 0.f; }

    float wk[16], wv[16];
#pragma unroll
    for (int i = 0; i < 16; i++) {
        wk[i] = kw[(kq * 16 + i) * CC + c];
        wv[i] = vw[(kq * 16 + i) * CC + c];
    }
    const float kbias = kb[c];
    const float vbias = vb[c];

    for (int g = blockIdx.x; g < GROUPS; g += gridDim.x) {
        xs[tid] = feat[(size_t)g * 256 + tid];
        __syncthreads();

#pragma unroll
        for (int row = 0; row < 4; row++) {
            float pk = 0.f, pv = 0.f;
            const float4* x4 = (const float4*)(xs + row * 64 + kq * 16);
#pragma unroll
            for (int i4 = 0; i4 < 4; i4++) {
                float4 xv = x4[i4];
                pk = fmaf(xv.x, wk[i4 * 4 + 0], pk); pv = fmaf(xv.x, wv[i4 * 4 + 0], pv);
                pk = fmaf(xv.y, wk[i4 * 4 + 1], pk); pv = fmaf(xv.y, wv[i4 * 4 + 1], pv);
                pk = fmaf(xv.z, wk[i4 * 4 + 2], pk); pv = fmaf(xv.z, wv[i4 * 4 + 2], pv);
                pk = fmaf(xv.w, wk[i4 * 4 + 3], pk); pv = fmaf(xv.w, wv[i4 * 4 + 3], pv);
            }
            psK[(row * 4 + kq) * 64 + c] = pk;
            psV[(row * 4 + kq) * 64 + c] = pv;
        }
        __syncthreads();

        {
            const int row = tid >> 6;  // reuse threads as (row, c)
            float sk = psK[(row * 4 + 0) * 64 + c] + psK[(row * 4 + 1) * 64 + c]
                     + psK[(row * 4 + 2) * 64 + c] + psK[(row * 4 + 3) * 64 + c] + kbias;
            float sv = psV[(row * 4 + 0) * 64 + c] + psV[(row * 4 + 1) * 64 + c]
                     + psV[(row * 4 + 2) * 64 + c] + psV[(row * 4 + 3) * 64 + c] + vbias;
            size_t o = (size_t)g * 256 + row * 64 + c;
            g_ek[o] = __expf(-sk * 0.125f);   // exp(-k/8): softmax numerator (q cancels)
            g_v[o]  = sv;
        }
        __syncthreads();
    }
}

// ============================================================================
// Kernel 2: local attention.  One warp per point; lane owns channels 2t,2t+1.
// attn_kc = ek_kc / sum_k ek_kc - 1;  ctx_c = max_k attn_kc * v_kc.
// idx dtype (int64 vs int32) detected at runtime from zero high-words.
// ============================================================================
__global__ void __launch_bounds__(256) attn_kernel(const void* __restrict__ idx_raw)
{
    const int lane   = threadIdx.x & 31;
    const int warp   = (blockIdx.x * (blockDim.x >> 5)) + (threadIdx.x >> 5);
    const int nwarps = gridDim.x * (blockDim.x >> 5);

    const unsigned* pw = (const unsigned*)idx_raw;
    const bool is64 = ((pw[1] | pw[3] | pw[5] | pw[7]) == 0u);

    for (int p = warp; p < ROWS; p += nwarps) {
        const int b = p >> 14;   // N = 16384
        int nb = 0;
        if (lane < KK) {
            long long iv = is64 ? ((const long long*)idx_raw)[(size_t)p * KK + lane]
                                : (long long)((const int*)idx_raw)[(size_t)p * KK + lane];
            nb = b * NN + (int)iv;            // neighbor row index
        }

        float2 e[KK];
        float sx = 0.f, sy = 0.f;
#pragma unroll
        for (int j = 0; j < KK; j++) {
            int off = __shfl_sync(0xffffffffu, nb, j);
            float2 ev = ((const float2*)(g_ek + (size_t)off * CC))[lane];
            e[j] = ev; sx += ev.x; sy += ev.y;
        }
        const float ix = __fdividef(1.f, sx);
        const float iy = __fdividef(1.f, sy);

        float mx = -3.402823466e38f, my = -3.402823466e38f;
#pragma unroll
        for (int j = 0; j < KK; j++) {
            int off = __shfl_sync(0xffffffffu, nb, j);
            float2 vv = ((const float2*)(g_v + (size_t)off * CC))[lane];
            float ax = fmaf(e[j].x, ix, -1.f);   // softmax - 1
            float ay = fmaf(e[j].y, iy, -1.f);
            mx = fmaxf(mx, ax * vv.x);
            my = fmaxf(my, ay * vv.y);
        }
        ((float2*)(g_ctx + (size_t)p * CC))[lane] = make_float2(mx, my);
    }
}

// ============================================================================
// Kernel 3: FFN linear (ctx @ fw + fb) + per-channel BN stat accumulation.
// Same register-weight GEMV layout as proj_kernel.
// ============================================================================
__global__ void __launch_bounds__(256) ffn_kernel(
    const float* __restrict__ fw, const float* __restrict__ fb)
{
    __shared__ float xs[256];
    __shared__ float ps[16 * 64];
    __shared__ float red[256];

    const int tid = threadIdx.x;
    const int kq  = tid >> 6;
    const int c   = tid & 63;

    float w[16];
#pragma unroll
    for (int i = 0; i < 16; i++) w[i] = fw[(kq * 16 + i) * CC + c];
    const float bias = fb[c];

    float acc_s = 0.f, acc_s2 = 0.f;

    for (int g = blockIdx.x; g < GROUPS; g += gridDim.x) {
        xs[tid] = g_ctx[(size_t)g * 256 + tid];
        __syncthreads();

#pragma unroll
        for (int row = 0; row < 4; row++) {
            float p = 0.f;
            const float4* x4 = (const float4*)(xs + row * 64 + kq * 16);
#pragma unroll
            for (int i4 = 0; i4 < 4; i4++) {
                float4 xv = x4[i4];
                p = fmaf(xv.x, w[i4 * 4 + 0], p);
                p = fmaf(xv.y, w[i4 * 4 + 1], p);
                p = fmaf(xv.z, w[i4 * 4 + 2], p);
                p = fmaf(xv.w, w[i4 * 4 + 3], p);
            }
            ps[(row * 4 + kq) * 64 + c] = p;
        }
        __syncthreads();

        {
            const int row = tid >> 6;
            float h = ps[(row * 4 + 0) * 64 + c] + ps[(row * 4 + 1) * 64 + c]
                    + ps[(row * 4 + 2) * 64 + c] + ps[(row * 4 + 3) * 64 + c] + bias;
            g_h[(size_t)g * 256 + row * 64 + c] = h;
            acc_s  += h;
            acc_s2 += h * h;
        }
        __syncthreads();
    }

    red[tid] = acc_s;  __syncthreads();
    if (tid < CC)
        atomicAdd(&g_sum[tid],  red[tid] + red[tid + 64] + red[tid + 128] + red[tid + 192]);
    __syncthreads();
    red[tid] = acc_s2; __syncthreads();
    if (tid < CC)
        atomicAdd(&g_sum2[tid], red[tid] + red[tid + 64] + red[tid + 128] + red[tid + 192]);
}

// ============================================================================
// Kernel 4: finalize.  Each block derives BN scale/shift from accumulated
// stats (cheap, 64 values), then applies BN + LeakyReLU + residual, float4.
// ============================================================================
__global__ void __launch_bounds__(256) final_kernel(
    const float* __restrict__ feat,
    const float* __restrict__ gamma, const float* __restrict__ beta,
    float* __restrict__ out)
{
    __shared__ float s_scale[CC], s_shift[CC];
    if (threadIdx.x < CC) {
        const int  cc   = threadIdx.x;
        const float inv = 1.f / (float)ROWS;
        float m   = g_sum[cc] * inv;
        float var = g_sum2[cc] * inv - m * m;
        float rstd = rsqrtf(var + 1e-5f);
        float sc = rstd * gamma[cc];
        s_scale[cc] = sc;
        s_shift[cc] = beta[cc] - m * sc;
    }
    __syncthreads();

    const size_t total4 = TOTAL / 4;
    const float4* h4 = (const float4*)g_h;
    const float4* f4 = (const float4*)feat;
    float4*       o4 = (float4*)out;
    const size_t stride = (size_t)gridDim.x * blockDim.x;

    for (size_t i = blockIdx.x * (size_t)blockDim.x + threadIdx.x; i < total4; i += stride) {
        const int c0 = (int)(i & 15) * 4;
        float4 h = h4[i];
        float4 f = f4[i];
        float r0 = h.x * s_scale[c0 + 0] + s_shift[c0 + 0];
        float r1 = h.y * s_scale[c0 + 1] + s_shift[c0 + 1];
        float r2 = h.z * s_scale[c0 + 2] + s_shift[c0 + 2];
        float r3 = h.w * s_scale[c0 + 3] + s_shift[c0 + 3];
        r0 = (r0 >= 0.f) ? r0 : 0.2f * r0;
        r1 = (r1 >= 0.f) ? r1 : 0.2f * r1;
        r2 = (r2 >= 0.f) ? r2 : 0.2f * r2;
        r3 = (r3 >= 0.f) ? r3 : 0.2f * r3;
        o4[i] = make_float4(f.x + r0, f.y + r1, f.z + r2, f.w + r3);
    }
}

// ============================================================================
// launch: features(0) pos(1) qw(2) qb(3) kw(4) kb(5) vw(6) vb(7)
//         fw(8) fb(9) gamma(10) beta(11) idx(12)
// pos / qw / qb are mathematically unused (softmax cancels q).
// ============================================================================
extern "C" void kernel_launch(void* const* d_in, const int* in_sizes, int n_in,
                              void* d_out, int out_size)
{
    const float* feat  = (const float*)d_in[0];
    const float* kw    = (const float*)d_in[4];
    const float* kb    = (const float*)d_in[5];
    const float* vw    = (const float*)d_in[6];
    const float* vb    = (const float*)d_in[7];
    const float* fw    = (const float*)d_in[8];
    const float* fb    = (const float*)d_in[9];
    const float* gamma = (const float*)d_in[10];
    const float* beta  = (const float*)d_in[11];
    const void*  idx   = (const void*)d_in[12];
    float* out = (float*)d_out;

    proj_kernel <<<1184, 256>>>(feat, kw, kb, vw, vb);
    attn_kernel <<<1024, 256>>>(idx);
    ffn_kernel  <<<1184, 256>>>(fw, fb);
    final_kernel<<<1024, 256>>>(feat, gamma, beta, out);
}

// round 4
// speedup vs baseline: 1.1434x; 1.1434x over previous
#include <cuda_runtime.h>
#include <cuda_fp16.h>
#include <cstdint>

#define BB 4
#define NN 16384
#define KK 16
#define CC 64
#define ROWS (BB * NN)          // 65536
#define GROUPS (ROWS / 4)       // proj: groups of 4 rows
#define GROUPS8 (ROWS / 8)      // fused: groups of 8 points
#define TOTAL ((size_t)ROWS * CC)

// ---------------- scratch (static device globals) ---------------------------
__device__ __half2 g_kv[TOTAL];   // (ek, v) packed per (row, channel) — 16 MB
__device__ __half  g_h [TOTAL];   // pre-BN FFN output — 8 MB
__device__ float   g_sum [CC];    // BN stats accumulators
__device__ float   g_sum2[CC];

// ============================================================================
// Kernel 1: fused k/v projection. k -> ek = exp(-k/8); pack (ek, v) as half2.
// 256 threads = (kq = tid>>6 : 16-slice of K dim, c = tid&63 : out channel);
// 16 weights/matrix in registers, x broadcast from smem. 4 rows per round.
// Block 0 zeroes BN accumulators for this launch.
// ============================================================================
__global__ void __launch_bounds__(256) proj_kernel(
    const float* __restrict__ feat,
    const float* __restrict__ kw, const float* __restrict__ kb,
    const float* __restrict__ vw, const float* __restrict__ vb)
{
    __shared__ float xs[256];
    __shared__ float psK[16 * 64];
    __shared__ float psV[16 * 64];

    const int tid = threadIdx.x;
    const int kq  = tid >> 6;
    const int c   = tid & 63;

    if (blockIdx.x == 0 && tid < CC) { g_sum[tid] = 0.f; g_sum2[tid] = 0.f; }

    float wk[16], wv[16];
#pragma unroll
    for (int i = 0; i < 16; i++) {
        wk[i] = kw[(kq * 16 + i) * CC + c];
        wv[i] = vw[(kq * 16 + i) * CC + c];
    }
    const float kbias = kb[c];
    const float vbias = vb[c];

    for (int g = blockIdx.x; g < GROUPS; g += gridDim.x) {
        xs[tid] = feat[(size_t)g * 256 + tid];
        __syncthreads();

#pragma unroll
        for (int row = 0; row < 4; row++) {
            float pk = 0.f, pv = 0.f;
            const float4* x4 = (const float4*)(xs + row * 64 + kq * 16);
#pragma unroll
            for (int i4 = 0; i4 < 4; i4++) {
                float4 xv = x4[i4];
                pk = fmaf(xv.x, wk[i4 * 4 + 0], pk); pv = fmaf(xv.x, wv[i4 * 4 + 0], pv);
                pk = fmaf(xv.y, wk[i4 * 4 + 1], pk); pv = fmaf(xv.y, wv[i4 * 4 + 1], pv);
                pk = fmaf(xv.z, wk[i4 * 4 + 2], pk); pv = fmaf(xv.z, wv[i4 * 4 + 2], pv);
                pk = fmaf(xv.w, wk[i4 * 4 + 3], pk); pv = fmaf(xv.w, wv[i4 * 4 + 3], pv);
            }
            psK[(row * 4 + kq) * 64 + c] = pk;
            psV[(row * 4 + kq) * 64 + c] = pv;
        }
        __syncthreads();

        {
            const int row = tid >> 6;
            float sk = psK[(row * 4 + 0) * 64 + c] + psK[(row * 4 + 1) * 64 + c]
                     + psK[(row * 4 + 2) * 64 + c] + psK[(row * 4 + 3) * 64 + c] + kbias;
            float sv = psV[(row * 4 + 0) * 64 + c] + psV[(row * 4 + 1) * 64 + c]
                     + psV[(row * 4 + 2) * 64 + c] + psV[(row * 4 + 3) * 64 + c] + vbias;
            float ek = __expf(-sk * 0.125f);   // exp(-k/8): q cancels in softmax
            g_kv[(size_t)g * 256 + row * 64 + c] = __floats2half2_rn(ek, sv);
        }
        __syncthreads();
    }
}

// ============================================================================
// Kernel 2: fused local attention + FFN GEMV + BN stat accumulation.
// Per group of 8 points: each of 8 warps computes one point's context
// (single fused (ek,v) gather, MLP=16) into smem, then the whole block runs
// the register-weight GEMV (fw held in registers, ctx broadcast from smem),
// writes h (fp16) and accumulates BN stats in registers.
// ============================================================================
__global__ void __launch_bounds__(256, 2) attn_ffn_kernel(
    const void* __restrict__ idx_raw,
    const float* __restrict__ fw, const float* __restrict__ fb)
{
    __shared__ float xs[8 * 64];     // ctx rows for 8 points
    __shared__ float ps[32 * 64];    // GEMV partials; reused for stat reduce

    const int tid  = threadIdx.x;
    const int lane = tid & 31;
    const int w    = tid >> 5;       // warp = which point in the group
    const int kq   = tid >> 6;       // GEMV: K-slice
    const int c    = tid & 63;       // GEMV: out channel

    const unsigned* pw = (const unsigned*)idx_raw;
    const bool is64 = ((pw[1] | pw[3] | pw[5] | pw[7]) == 0u);

    float fwreg[16];
#pragma unroll
    for (int i = 0; i < 16; i++) fwreg[i] = fw[(kq * 16 + i) * CC + c];
    const float fbias = fb[c];

    float acc_s = 0.f, acc_s2 = 0.f;

    for (int g = blockIdx.x; g < GROUPS8; g += gridDim.x) {
        // ---- attention: one warp per point, lane owns channels 2l, 2l+1 ----
        const int p = g * 8 + w;
        const int b = p >> 14;                 // N = 16384
        int nb = 0;
        if (lane < KK) {
            long long iv = is64 ? ((const long long*)idx_raw)[(size_t)p * KK + lane]
                                : (long long)((const int*)idx_raw)[(size_t)p * KK + lane];
            nb = b * NN + (int)iv;
        }

        float ex[KK], ey[KK], vx[KK], vy[KK];
        float sx = 0.f, sy = 0.f;
#pragma unroll
        for (int j = 0; j < KK; j++) {
            int off = __shfl_sync(0xffffffffu, nb, j);
            uint2 r = ((const uint2*)(g_kv + (size_t)off * CC))[lane];
            float2 f0 = __half22float2(*(__half2*)&r.x);
            float2 f1 = __half22float2(*(__half2*)&r.y);
            ex[j] = f0.x; vx[j] = f0.y;
            ey[j] = f1.x; vy[j] = f1.y;
            sx += f0.x;   sy += f1.x;
        }
        const float ix = __fdividef(1.f, sx);
        const float iy = __fdividef(1.f, sy);

        float mx = -3.402823466e38f, my = -3.402823466e38f;
#pragma unroll
        for (int j = 0; j < KK; j++) {
            mx = fmaxf(mx, fmaf(ex[j], ix, -1.f) * vx[j]);   // (softmax-1) * v
            my = fmaxf(my, fmaf(ey[j], iy, -1.f) * vy[j]);
        }
        ((float2*)(xs + w * 64))[lane] = make_float2(mx, my);
        __syncthreads();

        // ---- FFN GEMV on the 8 ctx rows (x broadcast from smem) ------------
#pragma unroll
        for (int row = 0; row < 8; row++) {
            float pacc = 0.f;
            const float4* x4 = (const float4*)(xs + row * 64 + kq * 16);
#pragma unroll
            for (int i4 = 0; i4 < 4; i4++) {
                float4 xv = x4[i4];
                pacc = fmaf(xv.x, fwreg[i4 * 4 + 0], pacc);
                pacc = fmaf(xv.y, fwreg[i4 * 4 + 1], pacc);
                pacc = fmaf(xv.z, fwreg[i4 * 4 + 2], pacc);
                pacc = fmaf(xv.w, fwreg[i4 * 4 + 3], pacc);
            }
            ps[(row * 4 + kq) * 64 + c] = pacc;
        }
        __syncthreads();

        // ---- reduce partials, store h (fp16), accumulate stats -------------
#pragma unroll
        for (int rpass = 0; rpass < 2; rpass++) {
            const int row = (tid >> 6) + rpass * 4;
            float h = ps[(row * 4 + 0) * 64 + c] + ps[(row * 4 + 1) * 64 + c]
                    + ps[(row * 4 + 2) * 64 + c] + ps[(row * 4 + 3) * 64 + c] + fbias;
            g_h[(size_t)(g * 8 + row) * CC + c] = __float2half_rn(h);
            acc_s  += h;
            acc_s2 += h * h;
        }
        __syncthreads();
    }

    // ---- block-level stat reduction -> global atomics ----------------------
    ps[tid] = acc_s;  __syncthreads();
    if (tid < CC)
        atomicAdd(&g_sum[tid],  ps[tid] + ps[tid + 64] + ps[tid + 128] + ps[tid + 192]);
    __syncthreads();
    ps[tid] = acc_s2; __syncthreads();
    if (tid < CC)
        atomicAdd(&g_sum2[tid], ps[tid] + ps[tid + 64] + ps[tid + 128] + ps[tid + 192]);
}

// ============================================================================
// Kernel 3: finalize. BN scale/shift from stats, then BN + LeakyReLU +
// residual. 2 independent float4 positions in flight per iteration (ILP).
// ============================================================================
__global__ void __launch_bounds__(256) final_kernel(
    const float* __restrict__ feat,
    const float* __restrict__ gamma, const float* __restrict__ beta,
    float* __restrict__ out)
{
    __shared__ float s_scale[CC], s_shift[CC];
    if (threadIdx.x < CC) {
        const int  cc   = threadIdx.x;
        const float inv = 1.f / (float)ROWS;
        float m    = g_sum[cc] * inv;
        float var  = g_sum2[cc] * inv - m * m;
        float rstd = rsqrtf(var + 1e-5f);
        float sc   = rstd * gamma[cc];
        s_scale[cc] = sc;
        s_shift[cc] = beta[cc] - m * sc;
    }
    __syncthreads();

    const size_t total4 = TOTAL / 4;                 // groups of 4 channels
    const uint2*  h2 = (const uint2*)g_h;            // 4 halves per uint2
    const float4* f4 = (const float4*)feat;
    float4*       o4 = (float4*)out;
    const size_t stride = (size_t)gridDim.x * blockDim.x * 2;

    for (size_t i = ((size_t)blockIdx.x * blockDim.x + threadIdx.x) * 2;
         i + 1 < total4; i += stride) {
#pragma unroll
        for (int u = 0; u < 2; u++) {
            const size_t ii = i + u;
            const int c0 = (int)(ii & 15) * 4;
            uint2 hr = h2[ii];
            float4 f = f4[ii];
            float2 ha = __half22float2(*(__half2*)&hr.x);
            float2 hb = __half22float2(*(__half2*)&hr.y);
            float r0 = ha.x * s_scale[c0 + 0] + s_shift[c0 + 0];
            float r1 = ha.y * s_scale[c0 + 1] + s_shift[c0 + 1];
            float r2 = hb.x * s_scale[c0 + 2] + s_shift[c0 + 2];
            float r3 = hb.y * s_scale[c0 + 3] + s_shift[c0 + 3];
            r0 = (r0 >= 0.f) ? r0 : 0.2f * r0;
            r1 = (r1 >= 0.f) ? r1 : 0.2f * r1;
            r2 = (r2 >= 0.f) ? r2 : 0.2f * r2;
            r3 = (r3 >= 0.f) ? r3 : 0.2f * r3;
            o4[ii] = make_float4(f.x + r0, f.y + r1, f.z + r2, f.w + r3);
        }
    }
}

// ============================================================================
// launch: features(0) pos(1) qw(2) qb(3) kw(4) kb(5) vw(6) vb(7)
//         fw(8) fb(9) gamma(10) beta(11) idx(12)
// pos / qw / qb are mathematically unused (q cancels inside softmax).
// ============================================================================
extern "C" void kernel_launch(void* const* d_in, const int* in_sizes, int n_in,
                              void* d_out, int out_size)
{
    const float* feat  = (const float*)d_in[0];
    const float* kw    = (const float*)d_in[4];
    const float* kb    = (const float*)d_in[5];
    const float* vw    = (const float*)d_in[6];
    const float* vb    = (const float*)d_in[7];
    const float* fw    = (const float*)d_in[8];
    const float* fb    = (const float*)d_in[9];
    const float* gamma = (const float*)d_in[10];
    const float* beta  = (const float*)d_in[11];
    const void*  idx   = (const void*)d_in[12];
    float* out = (float*)d_out;

    proj_kernel     <<<1184, 256>>>(feat, kw, kb, vw, vb);
    attn_ffn_kernel <<<1184, 256>>>(idx, fw, fb);
    final_kernel    <<<1024, 256>>>(feat, gamma, beta, out);
}